// round 15
// baseline (speedup 1.0000x reference)
#include <cuda_runtime.h>
#include <cuda_fp16.h>
#include <cstdint>

#define TT 512
#define DD 256
#define LL 256
#define HH 512
#define ZDIM 1024
#define CLU 8    // CTAs per cluster = per LSTM direction

// ---------------- device scratch (no allocations allowed) ----------------
__device__ __align__(16) float g_xw_a[TT * ZDIM];
__device__ __align__(16) float g_xw_b[TT * ZDIM];
__device__ __align__(16) __half g_Ut_h[4][ZDIM * LL];  // transposed U, fp16: [col][k]
__device__ __align__(16) float g_v[TT * 2 * LL];
__device__ __align__(16) float g_hcat[TT * 2 * LL];
__device__ __align__(16) float g_headf[TT * HH];
__device__ __align__(16) float g_modf[TT * HH];

// ---------------- fast activations ----------------
__device__ __forceinline__ float ftanh_hw(float x) { // MUFU tanh
    float r;
    asm("tanh.approx.f32 %0, %1;" : "=f"(r) : "f"(x));
    return r;
}
__device__ __forceinline__ float fsig_hw(float x) {  // sigmoid via MUFU tanh
    return fmaf(ftanh_hw(0.5f * x), 0.5f, 0.5f);
}

__device__ __forceinline__ uint32_t smem_u32(const void* p) {
    uint32_t a;
    asm("{ .reg .u64 t; cvta.to.shared.u64 t, %1; cvt.u32.u64 %0, t; }" : "=r"(a) : "l"(p));
    return a;
}

__device__ __forceinline__ __half2 shfl_xor_h2(__half2 v, int off, int width) {
    uint32_t b = *reinterpret_cast<uint32_t*>(&v);
    b = __shfl_xor_sync(0xffffffffu, b, off, width);
    return *reinterpret_cast<__half2*>(&b);
}

// try_wait parity with sleep (acquire)
__device__ __forceinline__ void mbar_wait_parity(uint32_t mbar, uint32_t parity) {
    uint32_t done;
    asm volatile(
        "{\n\t"
        ".reg .pred p;\n\t"
        "mbarrier.try_wait.parity.acquire.cta.shared::cta.b64 p, [%1], %2;\n\t"
        "selp.b32 %0, 1, 0, p;\n\t"
        "}"
        : "=r"(done) : "r"(mbar), "r"(parity) : "memory");
    if (!done) {
        asm volatile(
            "{\n\t"
            ".reg .pred P1;\n\t"
            "WAIT_LOOP_%=:\n\t"
            "mbarrier.try_wait.parity.acquire.cta.shared::cta.b64 P1, [%0], %1, 0x989680;\n\t"
            "@P1 bra.uni WAIT_DONE_%=;\n\t"
            "bra.uni WAIT_LOOP_%=;\n\t"
            "WAIT_DONE_%=:\n\t"
            "}"
            :: "r"(mbar), "r"(parity) : "memory");
    }
}

// ---------------- U transpose: [256,1024] -> [1024,256] fp16, x4 ----------------
__global__ void transposeU_kernel(const float* __restrict__ u0, const float* __restrict__ u1,
                                  const float* __restrict__ u2, const float* __restrict__ u3) {
    __shared__ float tile[32][33];
    const float* src = (blockIdx.z == 0) ? u0 : (blockIdx.z == 1) ? u1 : (blockIdx.z == 2) ? u2 : u3;
    __half* dst = g_Ut_h[blockIdx.z];
    int j  = blockIdx.x * 32 + threadIdx.x;
    int k0 = blockIdx.y * 32;
#pragma unroll
    for (int r = 0; r < 32; r += 8)
        tile[threadIdx.y + r][threadIdx.x] = src[(k0 + threadIdx.y + r) * ZDIM + j];
    __syncthreads();
    int k  = k0 + threadIdx.x;
    int jo = blockIdx.x * 32;
#pragma unroll
    for (int r = 0; r < 32; r += 8)
        dst[(jo + threadIdx.y + r) * LL + k] = __float2half(tile[threadIdx.x][threadIdx.y + r]);
}

// ---------------- dual fp32 tiled GEMM, double-buffered (head projections) ----------------
__global__ void __launch_bounds__(256) gemm2_kernel(
    const float* __restrict__ A0, const float* __restrict__ A1,
    const float* __restrict__ B0, const float* __restrict__ B1,
    const float* __restrict__ bias0, const float* __restrict__ bias1,
    float* __restrict__ C0, float* __restrict__ C1,
    int M, int N, int K) {
    const float* A    = (blockIdx.z == 0) ? A0 : A1;
    const float* B    = (blockIdx.z == 0) ? B0 : B1;
    const float* bias = (blockIdx.z == 0) ? bias0 : bias1;
    float* C          = (blockIdx.z == 0) ? C0 : C1;

    __shared__ __align__(16) float As[2][16][68];
    __shared__ __align__(16) float Bs[2][16][68];
    const int tid = threadIdx.x;
    const int tx = tid & 15, ty = tid >> 4;
    const int bm = blockIdx.y * 64, bn = blockIdx.x * 64;

    const int ar = tid >> 2;
    const int ac = (tid & 3) * 4;
    const int br = tid >> 4;
    const int bc = (tid & 15) * 4;

    float acc[4][4];
#pragma unroll
    for (int i = 0; i < 4; i++)
#pragma unroll
        for (int j = 0; j < 4; j++) acc[i][j] = 0.f;

    {
        float4 av = *(const float4*)&A[(bm + ar) * K + ac];
        As[0][ac + 0][ar] = av.x; As[0][ac + 1][ar] = av.y;
        As[0][ac + 2][ar] = av.z; As[0][ac + 3][ar] = av.w;
        float4 bv = *(const float4*)&B[br * N + bn + bc];
        *(float4*)&Bs[0][br][bc] = bv;
    }
    __syncthreads();

    int p = 0;
    for (int k0 = 16; k0 < K; k0 += 16) {
        float4 av = *(const float4*)&A[(bm + ar) * K + k0 + ac];
        float4 bv = *(const float4*)&B[(k0 + br) * N + bn + bc];

        {
            const float (*Ac)[68] = As[p];
            const float (*Bc)[68] = Bs[p];
#pragma unroll
            for (int kk = 0; kk < 16; kk++) {
                float4 a4 = *(const float4*)&Ac[kk][ty * 4];
                float4 b4 = *(const float4*)&Bc[kk][tx * 4];
                acc[0][0] += a4.x * b4.x; acc[0][1] += a4.x * b4.y; acc[0][2] += a4.x * b4.z; acc[0][3] += a4.x * b4.w;
                acc[1][0] += a4.y * b4.x; acc[1][1] += a4.y * b4.y; acc[1][2] += a4.y * b4.z; acc[1][3] += a4.y * b4.w;
                acc[2][0] += a4.z * b4.x; acc[2][1] += a4.z * b4.y; acc[2][2] += a4.z * b4.z; acc[2][3] += a4.z * b4.w;
                acc[3][0] += a4.w * b4.x; acc[3][1] += a4.w * b4.y; acc[3][2] += a4.w * b4.z; acc[3][3] += a4.w * b4.w;
            }
        }

        p ^= 1;
        As[p][ac + 0][ar] = av.x; As[p][ac + 1][ar] = av.y;
        As[p][ac + 2][ar] = av.z; As[p][ac + 3][ar] = av.w;
        *(float4*)&Bs[p][br][bc] = bv;
        __syncthreads();
    }

    {
        const float (*Ac)[68] = As[p];
        const float (*Bc)[68] = Bs[p];
#pragma unroll
        for (int kk = 0; kk < 16; kk++) {
            float4 a4 = *(const float4*)&Ac[kk][ty * 4];
            float4 b4 = *(const float4*)&Bc[kk][tx * 4];
            acc[0][0] += a4.x * b4.x; acc[0][1] += a4.x * b4.y; acc[0][2] += a4.x * b4.z; acc[0][3] += a4.x * b4.w;
            acc[1][0] += a4.y * b4.x; acc[1][1] += a4.y * b4.y; acc[1][2] += a4.y * b4.z; acc[1][3] += a4.y * b4.w;
            acc[2][0] += a4.z * b4.x; acc[2][1] += a4.z * b4.y; acc[2][2] += a4.z * b4.z; acc[2][3] += a4.z * b4.w;
            acc[3][0] += a4.w * b4.x; acc[3][1] += a4.w * b4.y; acc[3][2] += a4.w * b4.z; acc[3][3] += a4.w * b4.w;
        }
    }

#pragma unroll
    for (int i = 0; i < 4; i++) {
        int row = bm + ty * 4 + i;
#pragma unroll
        for (int j = 0; j < 4; j++) {
            int col = bn + tx * 4 + j;
            float v = acc[i][j];
            if (bias) v += bias[col];
            C[row * N + col] = v;
        }
    }
}

// ---------------- dual fp16 tiled GEMM (HFMA2) for xw projections ----------------
// C = A @ B (+bias), computed in packed half2 along k with fp16 accumulation.
// Outputs feed the LSTM preactivations -> errors wash out ~100x (measured R13/R14).
// As: [m][k] fp16 (natural A layout); Bs: [n][k] fp16 (transposed on staging).
// Inner tile: 128 HFMA2/thread vs 256 FFMA, and 16 vs 32 LDS.128.
__global__ void __launch_bounds__(256) gemm2h_kernel(
    const float* __restrict__ A0, const float* __restrict__ A1,
    const float* __restrict__ B0, const float* __restrict__ B1,
    const float* __restrict__ bias0, const float* __restrict__ bias1,
    float* __restrict__ C0, float* __restrict__ C1,
    int M, int N, int K) {
    const float* A    = (blockIdx.z == 0) ? A0 : A1;
    const float* B    = (blockIdx.z == 0) ? B0 : B1;
    const float* bias = (blockIdx.z == 0) ? bias0 : bias1;
    float* C          = (blockIdx.z == 0) ? C0 : C1;

    // pad rows to 24 halves (48 B, 16B-aligned) for clean LDS.128
    __shared__ __align__(16) __half As[2][64][24];   // [m][k]
    __shared__ __align__(16) __half Bs[2][64][24];   // [n][k]
    const int tid = threadIdx.x;
    const int tx = tid & 15, ty = tid >> 4;
    const int bm = blockIdx.y * 64, bn = blockIdx.x * 64;

    const int ar = tid >> 2;            // A row 0..63
    const int ac = (tid & 3) * 4;       // A k offset 0,4,8,12
    const int br = tid >> 4;            // B k-row 0..15
    const int bc = (tid & 15) * 4;      // B n offset 0..60

    __half2 acc[4][4];
#pragma unroll
    for (int i = 0; i < 4; i++)
#pragma unroll
        for (int j = 0; j < 4; j++) acc[i][j] = __float2half2_rn(0.f);

    // stage tile k0 into buffer p
    auto stage = [&](int p, int k0) {
        float4 av = *(const float4*)&A[(bm + ar) * K + k0 + ac];
        __half2 alo = __floats2half2_rn(av.x, av.y);
        __half2 ahi = __floats2half2_rn(av.z, av.w);
        uint2 apk;
        apk.x = *reinterpret_cast<uint32_t*>(&alo);
        apk.y = *reinterpret_cast<uint32_t*>(&ahi);
        *(uint2*)&As[p][ar][ac] = apk;               // 8B store, aligned

        float4 bv = *(const float4*)&B[(k0 + br) * N + bn + bc];
        Bs[p][bc + 0][br] = __float2half(bv.x);
        Bs[p][bc + 1][br] = __float2half(bv.y);
        Bs[p][bc + 2][br] = __float2half(bv.z);
        Bs[p][bc + 3][br] = __float2half(bv.w);
    };

    auto compute = [&](int p) {
        __half2 breg[4][8];
#pragma unroll
        for (int j = 0; j < 4; j++) {
            uint4 b0 = *(const uint4*)&Bs[p][tx * 4 + j][0];
            uint4 b1 = *(const uint4*)&Bs[p][tx * 4 + j][8];
            breg[j][0] = *reinterpret_cast<__half2*>(&b0.x);
            breg[j][1] = *reinterpret_cast<__half2*>(&b0.y);
            breg[j][2] = *reinterpret_cast<__half2*>(&b0.z);
            breg[j][3] = *reinterpret_cast<__half2*>(&b0.w);
            breg[j][4] = *reinterpret_cast<__half2*>(&b1.x);
            breg[j][5] = *reinterpret_cast<__half2*>(&b1.y);
            breg[j][6] = *reinterpret_cast<__half2*>(&b1.z);
            breg[j][7] = *reinterpret_cast<__half2*>(&b1.w);
        }
#pragma unroll
        for (int i = 0; i < 4; i++) {
            uint4 a0 = *(const uint4*)&As[p][ty * 4 + i][0];
            uint4 a1 = *(const uint4*)&As[p][ty * 4 + i][8];
            __half2 areg[8];
            areg[0] = *reinterpret_cast<__half2*>(&a0.x);
            areg[1] = *reinterpret_cast<__half2*>(&a0.y);
            areg[2] = *reinterpret_cast<__half2*>(&a0.z);
            areg[3] = *reinterpret_cast<__half2*>(&a0.w);
            areg[4] = *reinterpret_cast<__half2*>(&a1.x);
            areg[5] = *reinterpret_cast<__half2*>(&a1.y);
            areg[6] = *reinterpret_cast<__half2*>(&a1.z);
            areg[7] = *reinterpret_cast<__half2*>(&a1.w);
#pragma unroll
            for (int kk = 0; kk < 8; kk++) {
                acc[i][0] = __hfma2(areg[kk], breg[0][kk], acc[i][0]);
                acc[i][1] = __hfma2(areg[kk], breg[1][kk], acc[i][1]);
                acc[i][2] = __hfma2(areg[kk], breg[2][kk], acc[i][2]);
                acc[i][3] = __hfma2(areg[kk], breg[3][kk], acc[i][3]);
            }
        }
    };

    stage(0, 0);
    __syncthreads();

    int p = 0;
    for (int k0 = 16; k0 < K; k0 += 16) {
        // prefetch next tile's globals
        float4 av = *(const float4*)&A[(bm + ar) * K + k0 + ac];
        float4 bv = *(const float4*)&B[(k0 + br) * N + bn + bc];

        compute(p);

        p ^= 1;
        {
            __half2 alo = __floats2half2_rn(av.x, av.y);
            __half2 ahi = __floats2half2_rn(av.z, av.w);
            uint2 apk;
            apk.x = *reinterpret_cast<uint32_t*>(&alo);
            apk.y = *reinterpret_cast<uint32_t*>(&ahi);
            *(uint2*)&As[p][ar][ac] = apk;
            Bs[p][bc + 0][br] = __float2half(bv.x);
            Bs[p][bc + 1][br] = __float2half(bv.y);
            Bs[p][bc + 2][br] = __float2half(bv.z);
            Bs[p][bc + 3][br] = __float2half(bv.w);
        }
        __syncthreads();
    }

    compute(p);

#pragma unroll
    for (int i = 0; i < 4; i++) {
        int row = bm + ty * 4 + i;
#pragma unroll
        for (int j = 0; j < 4; j++) {
            int col = bn + tx * 4 + j;
            float v = __low2float(acc[i][j]) + __high2float(acc[i][j]);
            if (bias) v += bias[col];
            C[row * N + col] = v;
        }
    }
}

// ---------------- cluster LSTM: one 8-CTA cluster per direction, fp16 U·h ----------------
// (exact R14 form: proven 704.8us)
__global__ void __launch_bounds__(256, 1) __cluster_dims__(CLU, 1, 1)
lstm_cluster_kernel(int layer) {
    const int dir = blockIdx.x / CLU;
    uint32_t rank;
    asm("mov.u32 %0, %%cluster_ctarank;" : "=r"(rank));

    const float* xw = (dir == 0) ? g_xw_a : g_xw_b;
    const __half* Ut = g_Ut_h[layer * 2 + dir];
    float* out = (layer == 0) ? g_v : g_hcat;
    const int coloff = dir * LL;

    const int tid  = threadIdx.x;
    const int warp = tid >> 5, lane = tid & 31;
    const int usub = lane >> 3, sl = lane & 7;
    const int u = rank * 32 + warp * 4 + usub;

    __shared__ __align__(16) __half h_s[2][LL];
    __shared__ __align__(8) unsigned long long mbar[2];

    __half2 Ug[4][4][4];
#pragma unroll
    for (int g = 0; g < 4; g++)
#pragma unroll
        for (int j = 0; j < 4; j++) {
            uint4 w = *(const uint4*)&Ut[(size_t)(g * LL + u) * LL + j * 64 + sl * 8];
            Ug[g][j][0] = *reinterpret_cast<__half2*>(&w.x);
            Ug[g][j][1] = *reinterpret_cast<__half2*>(&w.y);
            Ug[g][j][2] = *reinterpret_cast<__half2*>(&w.z);
            Ug[g][j][3] = *reinterpret_cast<__half2*>(&w.w);
        }

    const uint32_t bar0 = smem_u32(&mbar[0]);
    const uint32_t bar1 = smem_u32(&mbar[1]);

    h_s[0][tid] = __float2half(0.f);
    if (tid == 0) {
        asm volatile("mbarrier.init.shared.b64 [%0], 1;" :: "r"(bar0) : "memory");
        asm volatile("mbarrier.init.shared.b64 [%0], 1;" :: "r"(bar1) : "memory");
        asm volatile("mbarrier.arrive.expect_tx.shared.b64 _, [%0], %1;" :: "r"(bar1), "r"(LL * 2) : "memory");
        asm volatile("mbarrier.arrive.expect_tx.shared.b64 _, [%0], %1;" :: "r"(bar0), "r"(LL * 2) : "memory");
    }
    __syncthreads();
    asm volatile("barrier.cluster.arrive.aligned;" ::: "memory");
    asm volatile("barrier.cluster.wait.aligned;" ::: "memory");

    const uint32_t hpair = smem_u32(&h_s[0][u & ~1]);
    uint32_t dHme;
    asm("mapa.shared::cluster.u32 %0, %1, %2;" : "=r"(dHme) : "r"(hpair), "r"(sl));
    const uint32_t offB0 = bar0 - hpair;
    const uint32_t offB1 = bar1 - hpair;
    const uint32_t offH1 = (uint32_t)(LL * 2);
    const bool pusher = ((usub & 1) == 0);

    float c = 0.f;
    uint32_t ph0 = 0, ph1 = 0;

    const int tok0 = (dir == 0) ? 0 : (TT - 1);
    float xwv0, xwv1, xwv2, xwv3;
    {
        const float* xp = &xw[tok0 * ZDIM + u];
        xwv0 = __ldg(xp + 0 * LL);
        xwv1 = __ldg(xp + 1 * LL);
        xwv2 = __ldg(xp + 2 * LL);
        xwv3 = __ldg(xp + 3 * LL);
    }

    for (int s = 0; s < TT; s++) {
        if (s > 0) {
            const uint32_t b = (s & 1) ? bar1 : bar0;
            uint32_t& ph = (s & 1) ? ph1 : ph0;
            mbar_wait_parity(b, ph);
            ph ^= 1;
            if (tid == 0)
                asm volatile("mbarrier.arrive.expect_tx.shared.b64 _, [%0], %1;" :: "r"(b), "r"(LL * 2) : "memory");
        }

        const __half* hc = h_s[s & 1];
        const int tok = (dir == 0) ? s : (TT - 1 - s);

        __half2 h2[4][4];
#pragma unroll
        for (int j = 0; j < 4; j++) {
            uint4 w = *(const uint4*)&hc[j * 64 + sl * 8];
            h2[j][0] = *reinterpret_cast<__half2*>(&w.x);
            h2[j][1] = *reinterpret_cast<__half2*>(&w.y);
            h2[j][2] = *reinterpret_cast<__half2*>(&w.z);
            h2[j][3] = *reinterpret_cast<__half2*>(&w.w);
        }

        __half2 a0 = __float2half2_rn(0.f), a1 = a0, a2 = a0, a3 = a0;
#pragma unroll
        for (int j = 0; j < 4; j++)
#pragma unroll
            for (int p = 0; p < 4; p++) {
                a0 = __hfma2(Ug[0][j][p], h2[j][p], a0);
                a1 = __hfma2(Ug[1][j][p], h2[j][p], a1);
                a2 = __hfma2(Ug[2][j][p], h2[j][p], a2);
                a3 = __hfma2(Ug[3][j][p], h2[j][p], a3);
            }
#pragma unroll
        for (int off = 4; off; off >>= 1) {
            a0 = __hadd2(a0, shfl_xor_h2(a0, off, 8));
            a1 = __hadd2(a1, shfl_xor_h2(a1, off, 8));
            a2 = __hadd2(a2, shfl_xor_h2(a2, off, 8));
            a3 = __hadd2(a3, shfl_xor_h2(a3, off, 8));
        }
        float acc0 = __low2float(a0) + __high2float(a0);
        float acc1 = __low2float(a1) + __high2float(a1);
        float acc2 = __low2float(a2) + __high2float(a2);
        float acc3 = __low2float(a3) + __high2float(a3);

        float iv = fsig_hw(acc0 + xwv0);
        float fv = fsig_hw(acc1 + xwv1);
        float gv = ftanh_hw(acc2 + xwv2);
        float ov = fsig_hw(acc3 + xwv3);
        c = fv * c + iv * gv;
        float hv = ov * ftanh_hw(c);

        if (s + 1 < TT) {
            uint32_t mine = (uint32_t)__half_as_ushort(__float2half(hv));
            uint32_t other = __shfl_xor_sync(0xffffffffu, mine, 8);
            if (pusher) {
                uint32_t pkt = mine | (other << 16);
                const uint32_t q = (s + 1) & 1;
                const uint32_t offH = q ? offH1 : 0u;
                const uint32_t offB = q ? offB1 : offB0;
                asm volatile(
                    "st.async.shared::cluster.mbarrier::complete_tx::bytes.b32 [%0], %1, [%2];"
                    :: "r"(dHme + offH), "r"(pkt), "r"(dHme + offB) : "memory");
            }
        }

        if (sl == 0)
            out[tok * (2 * LL) + coloff + u] = hv;

        if (s + 1 < TT) {
            const int ntok = (dir == 0) ? (s + 1) : (TT - 2 - s);
            const float* xp = &xw[ntok * ZDIM + u];
            xwv0 = __ldg(xp + 0 * LL);
            xwv1 = __ldg(xp + 1 * LL);
            xwv2 = __ldg(xp + 2 * LL);
            xwv3 = __ldg(xp + 3 * LL);
        }
    }

    asm volatile("barrier.cluster.arrive.aligned;" ::: "memory");
    asm volatile("barrier.cluster.wait.aligned;" ::: "memory");
}

// ---------------- pairwise head: out[i,j] = sum_h w[h]*tanh(hf[i,h]+mf[j,h]) + ob ----------------
__global__ void __launch_bounds__(256) pairwise_kernel(
    const float* __restrict__ headf, const float* __restrict__ modf,
    const float* __restrict__ outW, const float* __restrict__ outB,
    float* __restrict__ out) {
    __shared__ __align__(16) float SH[32][132];
    __shared__ float SMt[128][33];
    __shared__ __align__(16) float Wsh[128];

    const int t = threadIdx.x;
    const int i0 = blockIdx.y * 32, j0 = blockIdx.x * 32;
    const int li = t >> 3;
    const int lj = (t & 7) * 4;

    float acc0 = 0.f, acc1 = 0.f, acc2 = 0.f, acc3 = 0.f;

    for (int hc = 0; hc < HH; hc += 128) {
#pragma unroll
        for (int r = 0; r < 4; r++) {
            int idx = t + r * 256;
            int row = idx >> 5;
            int c4 = (idx & 31) * 4;
            float4 hvv = *(const float4*)&headf[(i0 + row) * HH + hc + c4];
            *(float4*)&SH[row][c4] = hvv;
            float4 mvv = *(const float4*)&modf[(j0 + row) * HH + hc + c4];
            SMt[c4 + 0][row] = mvv.x; SMt[c4 + 1][row] = mvv.y;
            SMt[c4 + 2][row] = mvv.z; SMt[c4 + 3][row] = mvv.w;
        }
        if (t < 32) *(float4*)&Wsh[t * 4] = *(const float4*)&outW[hc + t * 4];
        __syncthreads();

#pragma unroll 4
        for (int h = 0; h < 128; h++) {
            float hv = SH[li][h];
            float w = Wsh[h];
            acc0 += w * ftanh_hw(hv + SMt[h][lj + 0]);
            acc1 += w * ftanh_hw(hv + SMt[h][lj + 1]);
            acc2 += w * ftanh_hw(hv + SMt[h][lj + 2]);
            acc3 += w * ftanh_hw(hv + SMt[h][lj + 3]);
        }
        __syncthreads();
    }

    const float ob = outB[0];
    float* orow = &out[(i0 + li) * TT + j0 + lj];
    orow[0] = acc0 + ob;
    orow[1] = acc1 + ob;
    orow[2] = acc2 + ob;
    orow[3] = acc3 + ob;
}

// ---------------- host side ----------------
extern "C" void kernel_launch(void* const* d_in, const int* in_sizes, int n_in,
                              void* d_out, int out_size) {
    (void)in_sizes; (void)n_in; (void)out_size;
    const float* emb     = (const float*)d_in[0];
    const float* W_f1    = (const float*)d_in[1];
    const float* U_f1    = (const float*)d_in[2];
    const float* b_f1    = (const float*)d_in[3];
    const float* W_b1    = (const float*)d_in[4];
    const float* U_b1    = (const float*)d_in[5];
    const float* b_b1    = (const float*)d_in[6];
    const float* W_f2    = (const float*)d_in[7];
    const float* U_f2    = (const float*)d_in[8];
    const float* b_f2    = (const float*)d_in[9];
    const float* W_b2    = (const float*)d_in[10];
    const float* U_b2    = (const float*)d_in[11];
    const float* b_b2    = (const float*)d_in[12];
    const float* FOH     = (const float*)d_in[13];
    const float* FOM     = (const float*)d_in[14];
    const float* hidBias = (const float*)d_in[15];
    const float* outW    = (const float*)d_in[16];
    const float* outBias = (const float*)d_in[17];

    float *xwa, *xwb, *v, *hcat, *headf, *modf;
    cudaGetSymbolAddress((void**)&xwa,   g_xw_a);
    cudaGetSymbolAddress((void**)&xwb,   g_xw_b);
    cudaGetSymbolAddress((void**)&v,     g_v);
    cudaGetSymbolAddress((void**)&hcat,  g_hcat);
    cudaGetSymbolAddress((void**)&headf, g_headf);
    cudaGetSymbolAddress((void**)&modf,  g_modf);

    // 1. transpose + fp16-convert all recurrent matrices
    transposeU_kernel<<<dim3(ZDIM / 32, LL / 32, 4), dim3(32, 8)>>>(U_f1, U_b1, U_f2, U_b2);

    // 2. layer-1 input projections (fp16 HFMA2; errors wash out through the LSTM)
    gemm2h_kernel<<<dim3(ZDIM / 64, TT / 64, 2), 256>>>(
        emb, emb, W_f1, W_b1, b_f1, b_b1, xwa, xwb, TT, ZDIM, DD);

    // 3. layer-1 BiLSTM
    lstm_cluster_kernel<<<2 * CLU, 256>>>(0);

    // 4. layer-2 input projections (fp16 HFMA2)
    gemm2h_kernel<<<dim3(ZDIM / 64, TT / 64, 2), 256>>>(
        v, v, W_f2, W_b2, b_f2, b_b2, xwa, xwb, TT, ZDIM, 2 * LL);

    // 5. layer-2 BiLSTM -> hcat
    lstm_cluster_kernel<<<2 * CLU, 256>>>(1);

    // 6. head projections (fp32 — error path to scores does NOT average across j)
    gemm2_kernel<<<dim3(HH / 64, TT / 64, 2), 256>>>(
        hcat, hcat, FOH, FOM, hidBias, nullptr, headf, modf, TT, HH, 2 * LL);

    // 7. pairwise scores
    pairwise_kernel<<<dim3(TT / 32, TT / 32), 256>>>(headf, modf, outW, outBias, (float*)d_out);
}

// round 16
// speedup vs baseline: 1.1814x; 1.1814x over previous
#include <cuda_runtime.h>
#include <cuda_fp16.h>
#include <cstdint>

#define TT 512
#define DD 256
#define LL 256
#define HH 512
#define ZDIM 1024
#define CLU 8    // CTAs per cluster = per LSTM direction

// ---------------- device scratch (no allocations allowed) ----------------
__device__ __align__(16) float g_xw_a[TT * ZDIM];
__device__ __align__(16) float g_xw_b[TT * ZDIM];
__device__ __align__(16) __half g_Ut_h[4][ZDIM * LL];  // transposed U, fp16: [col][k]
__device__ __align__(16) float g_v[TT * 2 * LL];
__device__ __align__(16) float g_hcat[TT * 2 * LL];
__device__ __align__(16) float g_headf[TT * HH];
__device__ __align__(16) float g_modf[TT * HH];

// ---------------- fast activations ----------------
__device__ __forceinline__ float ftanh_hw(float x) { // MUFU tanh
    float r;
    asm("tanh.approx.f32 %0, %1;" : "=f"(r) : "f"(x));
    return r;
}
__device__ __forceinline__ float fsig_hw(float x) {  // sigmoid via MUFU tanh
    return fmaf(ftanh_hw(0.5f * x), 0.5f, 0.5f);
}

__device__ __forceinline__ uint32_t smem_u32(const void* p) {
    uint32_t a;
    asm("{ .reg .u64 t; cvta.to.shared.u64 t, %1; cvt.u32.u64 %0, t; }" : "=r"(a) : "l"(p));
    return a;
}

__device__ __forceinline__ __half2 shfl_xor_h2(__half2 v, int off, int width) {
    uint32_t b = *reinterpret_cast<uint32_t*>(&v);
    b = __shfl_xor_sync(0xffffffffu, b, off, width);
    return *reinterpret_cast<__half2*>(&b);
}

// try_wait parity with sleep (acquire)
__device__ __forceinline__ void mbar_wait_parity(uint32_t mbar, uint32_t parity) {
    uint32_t done;
    asm volatile(
        "{\n\t"
        ".reg .pred p;\n\t"
        "mbarrier.try_wait.parity.acquire.cta.shared::cta.b64 p, [%1], %2;\n\t"
        "selp.b32 %0, 1, 0, p;\n\t"
        "}"
        : "=r"(done) : "r"(mbar), "r"(parity) : "memory");
    if (!done) {
        asm volatile(
            "{\n\t"
            ".reg .pred P1;\n\t"
            "WAIT_LOOP_%=:\n\t"
            "mbarrier.try_wait.parity.acquire.cta.shared::cta.b64 P1, [%0], %1, 0x989680;\n\t"
            "@P1 bra.uni WAIT_DONE_%=;\n\t"
            "bra.uni WAIT_LOOP_%=;\n\t"
            "WAIT_DONE_%=:\n\t"
            "}"
            :: "r"(mbar), "r"(parity) : "memory");
    }
}

// ---------------- U transpose: [256,1024] -> [1024,256] fp16, x4 ----------------
__global__ void transposeU_kernel(const float* __restrict__ u0, const float* __restrict__ u1,
                                  const float* __restrict__ u2, const float* __restrict__ u3) {
    __shared__ float tile[32][33];
    const float* src = (blockIdx.z == 0) ? u0 : (blockIdx.z == 1) ? u1 : (blockIdx.z == 2) ? u2 : u3;
    __half* dst = g_Ut_h[blockIdx.z];
    int j  = blockIdx.x * 32 + threadIdx.x;
    int k0 = blockIdx.y * 32;
#pragma unroll
    for (int r = 0; r < 32; r += 8)
        tile[threadIdx.y + r][threadIdx.x] = src[(k0 + threadIdx.y + r) * ZDIM + j];
    __syncthreads();
    int k  = k0 + threadIdx.x;
    int jo = blockIdx.x * 32;
#pragma unroll
    for (int r = 0; r < 32; r += 8)
        dst[(jo + threadIdx.y + r) * LL + k] = __float2half(tile[threadIdx.x][threadIdx.y + r]);
}

// ---------------- dual fp32 tiled GEMM, double-buffered (head projections) ----------------
__global__ void __launch_bounds__(256) gemm2_kernel(
    const float* __restrict__ A0, const float* __restrict__ A1,
    const float* __restrict__ B0, const float* __restrict__ B1,
    const float* __restrict__ bias0, const float* __restrict__ bias1,
    float* __restrict__ C0, float* __restrict__ C1,
    int M, int N, int K) {
    const float* A    = (blockIdx.z == 0) ? A0 : A1;
    const float* B    = (blockIdx.z == 0) ? B0 : B1;
    const float* bias = (blockIdx.z == 0) ? bias0 : bias1;
    float* C          = (blockIdx.z == 0) ? C0 : C1;

    __shared__ __align__(16) float As[2][16][68];
    __shared__ __align__(16) float Bs[2][16][68];
    const int tid = threadIdx.x;
    const int tx = tid & 15, ty = tid >> 4;
    const int bm = blockIdx.y * 64, bn = blockIdx.x * 64;

    const int ar = tid >> 2;
    const int ac = (tid & 3) * 4;
    const int br = tid >> 4;
    const int bc = (tid & 15) * 4;

    float acc[4][4];
#pragma unroll
    for (int i = 0; i < 4; i++)
#pragma unroll
        for (int j = 0; j < 4; j++) acc[i][j] = 0.f;

    {
        float4 av = *(const float4*)&A[(bm + ar) * K + ac];
        As[0][ac + 0][ar] = av.x; As[0][ac + 1][ar] = av.y;
        As[0][ac + 2][ar] = av.z; As[0][ac + 3][ar] = av.w;
        float4 bv = *(const float4*)&B[br * N + bn + bc];
        *(float4*)&Bs[0][br][bc] = bv;
    }
    __syncthreads();

    int p = 0;
    for (int k0 = 16; k0 < K; k0 += 16) {
        float4 av = *(const float4*)&A[(bm + ar) * K + k0 + ac];
        float4 bv = *(const float4*)&B[(k0 + br) * N + bn + bc];

        {
            const float (*Ac)[68] = As[p];
            const float (*Bc)[68] = Bs[p];
#pragma unroll
            for (int kk = 0; kk < 16; kk++) {
                float4 a4 = *(const float4*)&Ac[kk][ty * 4];
                float4 b4 = *(const float4*)&Bc[kk][tx * 4];
                acc[0][0] += a4.x * b4.x; acc[0][1] += a4.x * b4.y; acc[0][2] += a4.x * b4.z; acc[0][3] += a4.x * b4.w;
                acc[1][0] += a4.y * b4.x; acc[1][1] += a4.y * b4.y; acc[1][2] += a4.y * b4.z; acc[1][3] += a4.y * b4.w;
                acc[2][0] += a4.z * b4.x; acc[2][1] += a4.z * b4.y; acc[2][2] += a4.z * b4.z; acc[2][3] += a4.z * b4.w;
                acc[3][0] += a4.w * b4.x; acc[3][1] += a4.w * b4.y; acc[3][2] += a4.w * b4.z; acc[3][3] += a4.w * b4.w;
            }
        }

        p ^= 1;
        As[p][ac + 0][ar] = av.x; As[p][ac + 1][ar] = av.y;
        As[p][ac + 2][ar] = av.z; As[p][ac + 3][ar] = av.w;
        *(float4*)&Bs[p][br][bc] = bv;
        __syncthreads();
    }

    {
        const float (*Ac)[68] = As[p];
        const float (*Bc)[68] = Bs[p];
#pragma unroll
        for (int kk = 0; kk < 16; kk++) {
            float4 a4 = *(const float4*)&Ac[kk][ty * 4];
            float4 b4 = *(const float4*)&Bc[kk][tx * 4];
            acc[0][0] += a4.x * b4.x; acc[0][1] += a4.x * b4.y; acc[0][2] += a4.x * b4.z; acc[0][3] += a4.x * b4.w;
            acc[1][0] += a4.y * b4.x; acc[1][1] += a4.y * b4.y; acc[1][2] += a4.y * b4.z; acc[1][3] += a4.y * b4.w;
            acc[2][0] += a4.z * b4.x; acc[2][1] += a4.z * b4.y; acc[2][2] += a4.z * b4.z; acc[2][3] += a4.z * b4.w;
            acc[3][0] += a4.w * b4.x; acc[3][1] += a4.w * b4.y; acc[3][2] += a4.w * b4.z; acc[3][3] += a4.w * b4.w;
        }
    }

#pragma unroll
    for (int i = 0; i < 4; i++) {
        int row = bm + ty * 4 + i;
#pragma unroll
        for (int j = 0; j < 4; j++) {
            int col = bn + tx * 4 + j;
            float v = acc[i][j];
            if (bias) v += bias[col];
            C[row * N + col] = v;
        }
    }
}

// ---------------- dual fp16-input / fp32-accum tensor GEMM (mma.sync m16n8k16) ----------------
// For the xw projections: C = A @ B (+bias). fp32 accumulators kill R15's
// accumulation error; input quantization (~5e-4) washes out through the LSTM.
// 64x64 tile, 8 warps (4 m-blocks x 2 n-blocks of 16x32), K-tile 32,
// double-buffered. A staged [m][k] pad-40, B staged [k][n] pad-72 -> all
// ldmatrix row addresses land in distinct banks; staging is STS.128-coalesced.
__global__ void __launch_bounds__(256) gemm2t_kernel(
    const float* __restrict__ A0, const float* __restrict__ A1,
    const float* __restrict__ B0, const float* __restrict__ B1,
    const float* __restrict__ bias0, const float* __restrict__ bias1,
    float* __restrict__ C0, float* __restrict__ C1,
    int M, int N, int K) {
    const float* A    = (blockIdx.z == 0) ? A0 : A1;
    const float* B    = (blockIdx.z == 0) ? B0 : B1;
    const float* bias = (blockIdx.z == 0) ? bias0 : bias1;
    float* C          = (blockIdx.z == 0) ? C0 : C1;

    __shared__ __align__(16) __half As[2][64][40];   // [m][k], pad 40 (80 B rows)
    __shared__ __align__(16) __half Bs[2][32][72];   // [k][n], pad 72 (144 B rows)

    const int tid  = threadIdx.x;
    const int warp = tid >> 5, lane = tid & 31;
    const int wr = warp & 3, wc = warp >> 2;        // m16-block, n32-block
    const int bm = blockIdx.y * 64, bn = blockIdx.x * 64;

    // staging coords
    const int sar = tid >> 2, sac = (tid & 3) * 8;   // A: row 0..63, k-off 0/8/16/24
    const int sbr = tid >> 3, sbc = (tid & 7) * 8;   // B: k-row 0..31, n-off 0..56

    float acc[4][4];                                 // 4 n8-blocks x 4 floats
#pragma unroll
    for (int j = 0; j < 4; j++)
#pragma unroll
        for (int i = 0; i < 4; i++) acc[j][i] = 0.f;

    auto cvt_store = [&](int p, float4 lo, float4 hi, __half* dst) {
        __half2 h0 = __floats2half2_rn(lo.x, lo.y);
        __half2 h1 = __floats2half2_rn(lo.z, lo.w);
        __half2 h2 = __floats2half2_rn(hi.x, hi.y);
        __half2 h3 = __floats2half2_rn(hi.z, hi.w);
        uint4 pk;
        pk.x = *reinterpret_cast<uint32_t*>(&h0);
        pk.y = *reinterpret_cast<uint32_t*>(&h1);
        pk.z = *reinterpret_cast<uint32_t*>(&h2);
        pk.w = *reinterpret_cast<uint32_t*>(&h3);
        *(uint4*)dst = pk;
        (void)p;
    };

    // stage tile k0 into buffer p
    auto stage = [&](int p, int k0) {
        float4 alo = *(const float4*)&A[(bm + sar) * K + k0 + sac];
        float4 ahi = *(const float4*)&A[(bm + sar) * K + k0 + sac + 4];
        cvt_store(p, alo, ahi, &As[p][sar][sac]);
        float4 blo = *(const float4*)&B[(k0 + sbr) * N + bn + sbc];
        float4 bhi = *(const float4*)&B[(k0 + sbr) * N + bn + sbc + 4];
        cvt_store(p, blo, bhi, &Bs[p][sbr][sbc]);
    };

    // ldmatrix addresses (per lane, fixed offsets within a buffer)
    const int l7 = lane & 7;
    const int aRow = wr * 16 + l7 + ((lane >> 3) & 1) * 8;   // + matrix pair row
    const int aColSel = (lane >> 4) * 8;                     // k-half select
    const int bRow = l7 + ((lane >> 3) & 1) * 8;             // k row within frag (lanes 0-15 used)

    auto compute = [&](int p) {
        const uint32_t asBase = smem_u32(&As[p][0][0]);
        const uint32_t bsBase = smem_u32(&Bs[p][0][0]);
#pragma unroll
        for (int kb = 0; kb < 2; kb++) {             // k16 halves of the 32-tile
            // A fragment: m16k16 via ldmatrix.x4
            uint32_t a0, a1, a2, a3;
            {
                uint32_t addr = asBase + (uint32_t)(aRow * 40 + kb * 16 + aColSel) * 2u;
                asm volatile("ldmatrix.sync.aligned.m8n8.x4.shared.b16 {%0,%1,%2,%3}, [%4];"
                             : "=r"(a0), "=r"(a1), "=r"(a2), "=r"(a3) : "r"(addr));
            }
#pragma unroll
            for (int j = 0; j < 4; j++) {            // n8 blocks of this warp's n32
                uint32_t b0, b1;
                {
                    uint32_t addr = bsBase + (uint32_t)((kb * 16 + bRow) * 72 + wc * 32 + j * 8) * 2u;
                    asm volatile("ldmatrix.sync.aligned.m8n8.x2.trans.shared.b16 {%0,%1}, [%2];"
                                 : "=r"(b0), "=r"(b1) : "r"(addr));
                }
                asm volatile(
                    "mma.sync.aligned.m16n8k16.row.col.f32.f16.f16.f32 "
                    "{%0,%1,%2,%3}, {%4,%5,%6,%7}, {%8,%9}, {%0,%1,%2,%3};"
                    : "+f"(acc[j][0]), "+f"(acc[j][1]), "+f"(acc[j][2]), "+f"(acc[j][3])
                    : "r"(a0), "r"(a1), "r"(a2), "r"(a3), "r"(b0), "r"(b1));
            }
        }
    };

    stage(0, 0);
    __syncthreads();

    int p = 0;
    for (int k0 = 32; k0 < K; k0 += 32) {
        // prefetch next tile's globals
        float4 alo = *(const float4*)&A[(bm + sar) * K + k0 + sac];
        float4 ahi = *(const float4*)&A[(bm + sar) * K + k0 + sac + 4];
        float4 blo = *(const float4*)&B[(k0 + sbr) * N + bn + sbc];
        float4 bhi = *(const float4*)&B[(k0 + sbr) * N + bn + sbc + 4];

        compute(p);

        p ^= 1;
        cvt_store(p, alo, ahi, &As[p][sar][sac]);
        cvt_store(p, blo, bhi, &Bs[p][sbr][sbc]);
        __syncthreads();
    }

    compute(p);

    // epilogue: c[j] maps to rows (g, g+8), cols j*8 + 2*tig + {0,1}
    const int g = lane >> 2, tig = lane & 3;
    const int row0 = bm + wr * 16 + g;
    const int colb = bn + wc * 32;
#pragma unroll
    for (int j = 0; j < 4; j++) {
        int col = colb + j * 8 + tig * 2;
        float b0f = bias ? bias[col] : 0.f;
        float b1f = bias ? bias[col + 1] : 0.f;
        *(float2*)&C[row0 * N + col]       = make_float2(acc[j][0] + b0f, acc[j][1] + b1f);
        *(float2*)&C[(row0 + 8) * N + col] = make_float2(acc[j][2] + b0f, acc[j][3] + b1f);
    }
}

// ---------------- cluster LSTM: one 8-CTA cluster per direction, fp16 U·h ----------------
// (exact R14 form: proven 704.8us)
__global__ void __launch_bounds__(256, 1) __cluster_dims__(CLU, 1, 1)
lstm_cluster_kernel(int layer) {
    const int dir = blockIdx.x / CLU;
    uint32_t rank;
    asm("mov.u32 %0, %%cluster_ctarank;" : "=r"(rank));

    const float* xw = (dir == 0) ? g_xw_a : g_xw_b;
    const __half* Ut = g_Ut_h[layer * 2 + dir];
    float* out = (layer == 0) ? g_v : g_hcat;
    const int coloff = dir * LL;

    const int tid  = threadIdx.x;
    const int warp = tid >> 5, lane = tid & 31;
    const int usub = lane >> 3, sl = lane & 7;
    const int u = rank * 32 + warp * 4 + usub;

    __shared__ __align__(16) __half h_s[2][LL];
    __shared__ __align__(8) unsigned long long mbar[2];

    __half2 Ug[4][4][4];
#pragma unroll
    for (int g = 0; g < 4; g++)
#pragma unroll
        for (int j = 0; j < 4; j++) {
            uint4 w = *(const uint4*)&Ut[(size_t)(g * LL + u) * LL + j * 64 + sl * 8];
            Ug[g][j][0] = *reinterpret_cast<__half2*>(&w.x);
            Ug[g][j][1] = *reinterpret_cast<__half2*>(&w.y);
            Ug[g][j][2] = *reinterpret_cast<__half2*>(&w.z);
            Ug[g][j][3] = *reinterpret_cast<__half2*>(&w.w);
        }

    const uint32_t bar0 = smem_u32(&mbar[0]);
    const uint32_t bar1 = smem_u32(&mbar[1]);

    h_s[0][tid] = __float2half(0.f);
    if (tid == 0) {
        asm volatile("mbarrier.init.shared.b64 [%0], 1;" :: "r"(bar0) : "memory");
        asm volatile("mbarrier.init.shared.b64 [%0], 1;" :: "r"(bar1) : "memory");
        asm volatile("mbarrier.arrive.expect_tx.shared.b64 _, [%0], %1;" :: "r"(bar1), "r"(LL * 2) : "memory");
        asm volatile("mbarrier.arrive.expect_tx.shared.b64 _, [%0], %1;" :: "r"(bar0), "r"(LL * 2) : "memory");
    }
    __syncthreads();
    asm volatile("barrier.cluster.arrive.aligned;" ::: "memory");
    asm volatile("barrier.cluster.wait.aligned;" ::: "memory");

    const uint32_t hpair = smem_u32(&h_s[0][u & ~1]);
    uint32_t dHme;
    asm("mapa.shared::cluster.u32 %0, %1, %2;" : "=r"(dHme) : "r"(hpair), "r"(sl));
    const uint32_t offB0 = bar0 - hpair;
    const uint32_t offB1 = bar1 - hpair;
    const uint32_t offH1 = (uint32_t)(LL * 2);
    const bool pusher = ((usub & 1) == 0);

    float c = 0.f;
    uint32_t ph0 = 0, ph1 = 0;

    const int tok0 = (dir == 0) ? 0 : (TT - 1);
    float xwv0, xwv1, xwv2, xwv3;
    {
        const float* xp = &xw[tok0 * ZDIM + u];
        xwv0 = __ldg(xp + 0 * LL);
        xwv1 = __ldg(xp + 1 * LL);
        xwv2 = __ldg(xp + 2 * LL);
        xwv3 = __ldg(xp + 3 * LL);
    }

    for (int s = 0; s < TT; s++) {
        if (s > 0) {
            const uint32_t b = (s & 1) ? bar1 : bar0;
            uint32_t& ph = (s & 1) ? ph1 : ph0;
            mbar_wait_parity(b, ph);
            ph ^= 1;
            if (tid == 0)
                asm volatile("mbarrier.arrive.expect_tx.shared.b64 _, [%0], %1;" :: "r"(b), "r"(LL * 2) : "memory");
        }

        const __half* hc = h_s[s & 1];
        const int tok = (dir == 0) ? s : (TT - 1 - s);

        __half2 h2[4][4];
#pragma unroll
        for (int j = 0; j < 4; j++) {
            uint4 w = *(const uint4*)&hc[j * 64 + sl * 8];
            h2[j][0] = *reinterpret_cast<__half2*>(&w.x);
            h2[j][1] = *reinterpret_cast<__half2*>(&w.y);
            h2[j][2] = *reinterpret_cast<__half2*>(&w.z);
            h2[j][3] = *reinterpret_cast<__half2*>(&w.w);
        }

        __half2 a0 = __float2half2_rn(0.f), a1 = a0, a2 = a0, a3 = a0;
#pragma unroll
        for (int j = 0; j < 4; j++)
#pragma unroll
            for (int p = 0; p < 4; p++) {
                a0 = __hfma2(Ug[0][j][p], h2[j][p], a0);
                a1 = __hfma2(Ug[1][j][p], h2[j][p], a1);
                a2 = __hfma2(Ug[2][j][p], h2[j][p], a2);
                a3 = __hfma2(Ug[3][j][p], h2[j][p], a3);
            }
#pragma unroll
        for (int off = 4; off; off >>= 1) {
            a0 = __hadd2(a0, shfl_xor_h2(a0, off, 8));
            a1 = __hadd2(a1, shfl_xor_h2(a1, off, 8));
            a2 = __hadd2(a2, shfl_xor_h2(a2, off, 8));
            a3 = __hadd2(a3, shfl_xor_h2(a3, off, 8));
        }
        float acc0 = __low2float(a0) + __high2float(a0);
        float acc1 = __low2float(a1) + __high2float(a1);
        float acc2 = __low2float(a2) + __high2float(a2);
        float acc3 = __low2float(a3) + __high2float(a3);

        float iv = fsig_hw(acc0 + xwv0);
        float fv = fsig_hw(acc1 + xwv1);
        float gv = ftanh_hw(acc2 + xwv2);
        float ov = fsig_hw(acc3 + xwv3);
        c = fv * c + iv * gv;
        float hv = ov * ftanh_hw(c);

        if (s + 1 < TT) {
            uint32_t mine = (uint32_t)__half_as_ushort(__float2half(hv));
            uint32_t other = __shfl_xor_sync(0xffffffffu, mine, 8);
            if (pusher) {
                uint32_t pkt = mine | (other << 16);
                const uint32_t q = (s + 1) & 1;
                const uint32_t offH = q ? offH1 : 0u;
                const uint32_t offB = q ? offB1 : offB0;
                asm volatile(
                    "st.async.shared::cluster.mbarrier::complete_tx::bytes.b32 [%0], %1, [%2];"
                    :: "r"(dHme + offH), "r"(pkt), "r"(dHme + offB) : "memory");
            }
        }

        if (sl == 0)
            out[tok * (2 * LL) + coloff + u] = hv;

        if (s + 1 < TT) {
            const int ntok = (dir == 0) ? (s + 1) : (TT - 2 - s);
            const float* xp = &xw[ntok * ZDIM + u];
            xwv0 = __ldg(xp + 0 * LL);
            xwv1 = __ldg(xp + 1 * LL);
            xwv2 = __ldg(xp + 2 * LL);
            xwv3 = __ldg(xp + 3 * LL);
        }
    }

    asm volatile("barrier.cluster.arrive.aligned;" ::: "memory");
    asm volatile("barrier.cluster.wait.aligned;" ::: "memory");
}

// ---------------- pairwise head: out[i,j] = sum_h w[h]*tanh(hf[i,h]+mf[j,h]) + ob ----------------
__global__ void __launch_bounds__(256) pairwise_kernel(
    const float* __restrict__ headf, const float* __restrict__ modf,
    const float* __restrict__ outW, const float* __restrict__ outB,
    float* __restrict__ out) {
    __shared__ __align__(16) float SH[32][132];
    __shared__ float SMt[128][33];
    __shared__ __align__(16) float Wsh[128];

    const int t = threadIdx.x;
    const int i0 = blockIdx.y * 32, j0 = blockIdx.x * 32;
    const int li = t >> 3;
    const int lj = (t & 7) * 4;

    float acc0 = 0.f, acc1 = 0.f, acc2 = 0.f, acc3 = 0.f;

    for (int hc = 0; hc < HH; hc += 128) {
#pragma unroll
        for (int r = 0; r < 4; r++) {
            int idx = t + r * 256;
            int row = idx >> 5;
            int c4 = (idx & 31) * 4;
            float4 hvv = *(const float4*)&headf[(i0 + row) * HH + hc + c4];
            *(float4*)&SH[row][c4] = hvv;
            float4 mvv = *(const float4*)&modf[(j0 + row) * HH + hc + c4];
            SMt[c4 + 0][row] = mvv.x; SMt[c4 + 1][row] = mvv.y;
            SMt[c4 + 2][row] = mvv.z; SMt[c4 + 3][row] = mvv.w;
        }
        if (t < 32) *(float4*)&Wsh[t * 4] = *(const float4*)&outW[hc + t * 4];
        __syncthreads();

#pragma unroll 4
        for (int h = 0; h < 128; h++) {
            float hv = SH[li][h];
            float w = Wsh[h];
            acc0 += w * ftanh_hw(hv + SMt[h][lj + 0]);
            acc1 += w * ftanh_hw(hv + SMt[h][lj + 1]);
            acc2 += w * ftanh_hw(hv + SMt[h][lj + 2]);
            acc3 += w * ftanh_hw(hv + SMt[h][lj + 3]);
        }
        __syncthreads();
    }

    const float ob = outB[0];
    float* orow = &out[(i0 + li) * TT + j0 + lj];
    orow[0] = acc0 + ob;
    orow[1] = acc1 + ob;
    orow[2] = acc2 + ob;
    orow[3] = acc3 + ob;
}

// ---------------- host side ----------------
extern "C" void kernel_launch(void* const* d_in, const int* in_sizes, int n_in,
                              void* d_out, int out_size) {
    (void)in_sizes; (void)n_in; (void)out_size;
    const float* emb     = (const float*)d_in[0];
    const float* W_f1    = (const float*)d_in[1];
    const float* U_f1    = (const float*)d_in[2];
    const float* b_f1    = (const float*)d_in[3];
    const float* W_b1    = (const float*)d_in[4];
    const float* U_b1    = (const float*)d_in[5];
    const float* b_b1    = (const float*)d_in[6];
    const float* W_f2    = (const float*)d_in[7];
    const float* U_f2    = (const float*)d_in[8];
    const float* b_f2    = (const float*)d_in[9];
    const float* W_b2    = (const float*)d_in[10];
    const float* U_b2    = (const float*)d_in[11];
    const float* b_b2    = (const float*)d_in[12];
    const float* FOH     = (const float*)d_in[13];
    const float* FOM     = (const float*)d_in[14];
    const float* hidBias = (const float*)d_in[15];
    const float* outW    = (const float*)d_in[16];
    const float* outBias = (const float*)d_in[17];

    float *xwa, *xwb, *v, *hcat, *headf, *modf;
    cudaGetSymbolAddress((void**)&xwa,   g_xw_a);
    cudaGetSymbolAddress((void**)&xwb,   g_xw_b);
    cudaGetSymbolAddress((void**)&v,     g_v);
    cudaGetSymbolAddress((void**)&hcat,  g_hcat);
    cudaGetSymbolAddress((void**)&headf, g_headf);
    cudaGetSymbolAddress((void**)&modf,  g_modf);

    // 1. transpose + fp16-convert all recurrent matrices
    transposeU_kernel<<<dim3(ZDIM / 32, LL / 32, 4), dim3(32, 8)>>>(U_f1, U_b1, U_f2, U_b2);

    // 2. layer-1 input projections (tensor-core fp16 x fp32-accum)
    gemm2t_kernel<<<dim3(ZDIM / 64, TT / 64, 2), 256>>>(
        emb, emb, W_f1, W_b1, b_f1, b_b1, xwa, xwb, TT, ZDIM, DD);

    // 3. layer-1 BiLSTM
    lstm_cluster_kernel<<<2 * CLU, 256>>>(0);

    // 4. layer-2 input projections (tensor-core)
    gemm2t_kernel<<<dim3(ZDIM / 64, TT / 64, 2), 256>>>(
        v, v, W_f2, W_b2, b_f2, b_b2, xwa, xwb, TT, ZDIM, 2 * LL);

    // 5. layer-2 BiLSTM -> hcat
    lstm_cluster_kernel<<<2 * CLU, 256>>>(1);

    // 6. head projections (fp32 — error path to scores does NOT average across j)
    gemm2_kernel<<<dim3(HH / 64, TT / 64, 2), 256>>>(
        hcat, hcat, FOH, FOM, hidBias, nullptr, headf, modf, TT, HH, 2 * LL);

    // 7. pairwise scores
    pairwise_kernel<<<dim3(TT / 32, TT / 32), 256>>>(headf, modf, outW, outBias, (float*)d_out);
}

// round 17
// speedup vs baseline: 1.2046x; 1.0196x over previous
#include <cuda_runtime.h>
#include <cuda_fp16.h>
#include <cstdint>

#define TT 512
#define DD 256
#define LL 256
#define HH 512
#define ZDIM 1024
#define CLU 8    // CTAs per cluster = per LSTM direction

// ---------------- device scratch (no allocations allowed) ----------------
__device__ __align__(16) float g_xw_a[TT * ZDIM];
__device__ __align__(16) float g_xw_b[TT * ZDIM];
__device__ __align__(16) __half g_Ut_h[4][ZDIM * LL];  // transposed U, fp16: [col][k]
__device__ __align__(16) float g_v[TT * 2 * LL];
__device__ __align__(16) float g_hcat[TT * 2 * LL];
__device__ __align__(16) float g_headf[TT * HH];
__device__ __align__(16) float g_modf[TT * HH];

// ---------------- fast activations ----------------
__device__ __forceinline__ float ftanh_hw(float x) { // MUFU tanh
    float r;
    asm("tanh.approx.f32 %0, %1;" : "=f"(r) : "f"(x));
    return r;
}
__device__ __forceinline__ float fsig_hw(float x) {  // sigmoid via MUFU tanh
    return fmaf(ftanh_hw(0.5f * x), 0.5f, 0.5f);
}

__device__ __forceinline__ uint32_t smem_u32(const void* p) {
    uint32_t a;
    asm("{ .reg .u64 t; cvta.to.shared.u64 t, %1; cvt.u32.u64 %0, t; }" : "=r"(a) : "l"(p));
    return a;
}

__device__ __forceinline__ __half2 shfl_xor_h2(__half2 v, int off, int width) {
    uint32_t b = *reinterpret_cast<uint32_t*>(&v);
    b = __shfl_xor_sync(0xffffffffu, b, off, width);
    return *reinterpret_cast<__half2*>(&b);
}

// try_wait parity with sleep (acquire)
__device__ __forceinline__ void mbar_wait_parity(uint32_t mbar, uint32_t parity) {
    uint32_t done;
    asm volatile(
        "{\n\t"
        ".reg .pred p;\n\t"
        "mbarrier.try_wait.parity.acquire.cta.shared::cta.b64 p, [%1], %2;\n\t"
        "selp.b32 %0, 1, 0, p;\n\t"
        "}"
        : "=r"(done) : "r"(mbar), "r"(parity) : "memory");
    if (!done) {
        asm volatile(
            "{\n\t"
            ".reg .pred P1;\n\t"
            "WAIT_LOOP_%=:\n\t"
            "mbarrier.try_wait.parity.acquire.cta.shared::cta.b64 P1, [%0], %1, 0x989680;\n\t"
            "@P1 bra.uni WAIT_DONE_%=;\n\t"
            "bra.uni WAIT_LOOP_%=;\n\t"
            "WAIT_DONE_%=:\n\t"
            "}"
            :: "r"(mbar), "r"(parity) : "memory");
    }
}

// ---------------- U transpose: [256,1024] -> [1024,256] fp16, x4 ----------------
__global__ void transposeU_kernel(const float* __restrict__ u0, const float* __restrict__ u1,
                                  const float* __restrict__ u2, const float* __restrict__ u3) {
    __shared__ float tile[32][33];
    const float* src = (blockIdx.z == 0) ? u0 : (blockIdx.z == 1) ? u1 : (blockIdx.z == 2) ? u2 : u3;
    __half* dst = g_Ut_h[blockIdx.z];
    int j  = blockIdx.x * 32 + threadIdx.x;
    int k0 = blockIdx.y * 32;
#pragma unroll
    for (int r = 0; r < 32; r += 8)
        tile[threadIdx.y + r][threadIdx.x] = src[(k0 + threadIdx.y + r) * ZDIM + j];
    __syncthreads();
    int k  = k0 + threadIdx.x;
    int jo = blockIdx.x * 32;
#pragma unroll
    for (int r = 0; r < 32; r += 8)
        dst[(jo + threadIdx.y + r) * LL + k] = __float2half(tile[threadIdx.x][threadIdx.y + r]);
}

// ---------------- dual fp16-input / fp32-accum tensor GEMM (mma.sync m16n8k16) ----------------
// C = A @ B (+bias). 64x64 tile, 8 warps (4 m16 x 2 n32), K-tile 32,
// double-buffered. A staged [m][k] pad-40, B staged [k][n] pad-72.
__global__ void __launch_bounds__(256) gemm2t_kernel(
    const float* __restrict__ A0, const float* __restrict__ A1,
    const float* __restrict__ B0, const float* __restrict__ B1,
    const float* __restrict__ bias0, const float* __restrict__ bias1,
    float* __restrict__ C0, float* __restrict__ C1,
    int M, int N, int K) {
    const float* A    = (blockIdx.z == 0) ? A0 : A1;
    const float* B    = (blockIdx.z == 0) ? B0 : B1;
    const float* bias = (blockIdx.z == 0) ? bias0 : bias1;
    float* C          = (blockIdx.z == 0) ? C0 : C1;

    __shared__ __align__(16) __half As[2][64][40];   // [m][k], pad 40 (80 B rows)
    __shared__ __align__(16) __half Bs[2][32][72];   // [k][n], pad 72 (144 B rows)

    const int tid  = threadIdx.x;
    const int warp = tid >> 5, lane = tid & 31;
    const int wr = warp & 3, wc = warp >> 2;        // m16-block, n32-block
    const int bm = blockIdx.y * 64, bn = blockIdx.x * 64;

    const int sar = tid >> 2, sac = (tid & 3) * 8;   // A staging: row 0..63, k-off
    const int sbr = tid >> 3, sbc = (tid & 7) * 8;   // B staging: k-row 0..31, n-off

    float acc[4][4];
#pragma unroll
    for (int j = 0; j < 4; j++)
#pragma unroll
        for (int i = 0; i < 4; i++) acc[j][i] = 0.f;

    auto cvt_store = [&](float4 lo, float4 hi, __half* dst) {
        __half2 h0 = __floats2half2_rn(lo.x, lo.y);
        __half2 h1 = __floats2half2_rn(lo.z, lo.w);
        __half2 h2 = __floats2half2_rn(hi.x, hi.y);
        __half2 h3 = __floats2half2_rn(hi.z, hi.w);
        uint4 pk;
        pk.x = *reinterpret_cast<uint32_t*>(&h0);
        pk.y = *reinterpret_cast<uint32_t*>(&h1);
        pk.z = *reinterpret_cast<uint32_t*>(&h2);
        pk.w = *reinterpret_cast<uint32_t*>(&h3);
        *(uint4*)dst = pk;
    };

    auto stage = [&](int p, int k0) {
        float4 alo = *(const float4*)&A[(bm + sar) * K + k0 + sac];
        float4 ahi = *(const float4*)&A[(bm + sar) * K + k0 + sac + 4];
        cvt_store(alo, ahi, &As[p][sar][sac]);
        float4 blo = *(const float4*)&B[(k0 + sbr) * N + bn + sbc];
        float4 bhi = *(const float4*)&B[(k0 + sbr) * N + bn + sbc + 4];
        cvt_store(blo, bhi, &Bs[p][sbr][sbc]);
    };

    const int l7 = lane & 7;
    const int aRow = wr * 16 + l7 + ((lane >> 3) & 1) * 8;
    const int aColSel = (lane >> 4) * 8;
    const int bRow = l7 + ((lane >> 3) & 1) * 8;

    auto compute = [&](int p) {
        const uint32_t asBase = smem_u32(&As[p][0][0]);
        const uint32_t bsBase = smem_u32(&Bs[p][0][0]);
#pragma unroll
        for (int kb = 0; kb < 2; kb++) {
            uint32_t a0, a1, a2, a3;
            {
                uint32_t addr = asBase + (uint32_t)(aRow * 40 + kb * 16 + aColSel) * 2u;
                asm volatile("ldmatrix.sync.aligned.m8n8.x4.shared.b16 {%0,%1,%2,%3}, [%4];"
                             : "=r"(a0), "=r"(a1), "=r"(a2), "=r"(a3) : "r"(addr));
            }
#pragma unroll
            for (int j = 0; j < 4; j++) {
                uint32_t b0, b1;
                {
                    uint32_t addr = bsBase + (uint32_t)((kb * 16 + bRow) * 72 + wc * 32 + j * 8) * 2u;
                    asm volatile("ldmatrix.sync.aligned.m8n8.x2.trans.shared.b16 {%0,%1}, [%2];"
                                 : "=r"(b0), "=r"(b1) : "r"(addr));
                }
                asm volatile(
                    "mma.sync.aligned.m16n8k16.row.col.f32.f16.f16.f32 "
                    "{%0,%1,%2,%3}, {%4,%5,%6,%7}, {%8,%9}, {%0,%1,%2,%3};"
                    : "+f"(acc[j][0]), "+f"(acc[j][1]), "+f"(acc[j][2]), "+f"(acc[j][3])
                    : "r"(a0), "r"(a1), "r"(a2), "r"(a3), "r"(b0), "r"(b1));
            }
        }
    };

    stage(0, 0);
    __syncthreads();

    int p = 0;
    for (int k0 = 32; k0 < K; k0 += 32) {
        float4 alo = *(const float4*)&A[(bm + sar) * K + k0 + sac];
        float4 ahi = *(const float4*)&A[(bm + sar) * K + k0 + sac + 4];
        float4 blo = *(const float4*)&B[(k0 + sbr) * N + bn + sbc];
        float4 bhi = *(const float4*)&B[(k0 + sbr) * N + bn + sbc + 4];

        compute(p);

        p ^= 1;
        cvt_store(alo, ahi, &As[p][sar][sac]);
        cvt_store(blo, bhi, &Bs[p][sbr][sbc]);
        __syncthreads();
    }

    compute(p);

    const int g = lane >> 2, tig = lane & 3;
    const int row0 = bm + wr * 16 + g;
    const int colb = bn + wc * 32;
#pragma unroll
    for (int j = 0; j < 4; j++) {
        int col = colb + j * 8 + tig * 2;
        float b0f = bias ? bias[col] : 0.f;
        float b1f = bias ? bias[col + 1] : 0.f;
        *(float2*)&C[row0 * N + col]       = make_float2(acc[j][0] + b0f, acc[j][1] + b1f);
        *(float2*)&C[(row0 + 8) * N + col] = make_float2(acc[j][2] + b0f, acc[j][3] + b1f);
    }
}

// ---------------- cluster LSTM: one 8-CTA cluster per direction, fp16 U·h ----------------
// (exact R14 form: proven)
__global__ void __launch_bounds__(256, 1) __cluster_dims__(CLU, 1, 1)
lstm_cluster_kernel(int layer) {
    const int dir = blockIdx.x / CLU;
    uint32_t rank;
    asm("mov.u32 %0, %%cluster_ctarank;" : "=r"(rank));

    const float* xw = (dir == 0) ? g_xw_a : g_xw_b;
    const __half* Ut = g_Ut_h[layer * 2 + dir];
    float* out = (layer == 0) ? g_v : g_hcat;
    const int coloff = dir * LL;

    const int tid  = threadIdx.x;
    const int warp = tid >> 5, lane = tid & 31;
    const int usub = lane >> 3, sl = lane & 7;
    const int u = rank * 32 + warp * 4 + usub;

    __shared__ __align__(16) __half h_s[2][LL];
    __shared__ __align__(8) unsigned long long mbar[2];

    __half2 Ug[4][4][4];
#pragma unroll
    for (int g = 0; g < 4; g++)
#pragma unroll
        for (int j = 0; j < 4; j++) {
            uint4 w = *(const uint4*)&Ut[(size_t)(g * LL + u) * LL + j * 64 + sl * 8];
            Ug[g][j][0] = *reinterpret_cast<__half2*>(&w.x);
            Ug[g][j][1] = *reinterpret_cast<__half2*>(&w.y);
            Ug[g][j][2] = *reinterpret_cast<__half2*>(&w.z);
            Ug[g][j][3] = *reinterpret_cast<__half2*>(&w.w);
        }

    const uint32_t bar0 = smem_u32(&mbar[0]);
    const uint32_t bar1 = smem_u32(&mbar[1]);

    h_s[0][tid] = __float2half(0.f);
    if (tid == 0) {
        asm volatile("mbarrier.init.shared.b64 [%0], 1;" :: "r"(bar0) : "memory");
        asm volatile("mbarrier.init.shared.b64 [%0], 1;" :: "r"(bar1) : "memory");
        asm volatile("mbarrier.arrive.expect_tx.shared.b64 _, [%0], %1;" :: "r"(bar1), "r"(LL * 2) : "memory");
        asm volatile("mbarrier.arrive.expect_tx.shared.b64 _, [%0], %1;" :: "r"(bar0), "r"(LL * 2) : "memory");
    }
    __syncthreads();
    asm volatile("barrier.cluster.arrive.aligned;" ::: "memory");
    asm volatile("barrier.cluster.wait.aligned;" ::: "memory");

    const uint32_t hpair = smem_u32(&h_s[0][u & ~1]);
    uint32_t dHme;
    asm("mapa.shared::cluster.u32 %0, %1, %2;" : "=r"(dHme) : "r"(hpair), "r"(sl));
    const uint32_t offB0 = bar0 - hpair;
    const uint32_t offB1 = bar1 - hpair;
    const uint32_t offH1 = (uint32_t)(LL * 2);
    const bool pusher = ((usub & 1) == 0);

    float c = 0.f;
    uint32_t ph0 = 0, ph1 = 0;

    const int tok0 = (dir == 0) ? 0 : (TT - 1);
    float xwv0, xwv1, xwv2, xwv3;
    {
        const float* xp = &xw[tok0 * ZDIM + u];
        xwv0 = __ldg(xp + 0 * LL);
        xwv1 = __ldg(xp + 1 * LL);
        xwv2 = __ldg(xp + 2 * LL);
        xwv3 = __ldg(xp + 3 * LL);
    }

    for (int s = 0; s < TT; s++) {
        if (s > 0) {
            const uint32_t b = (s & 1) ? bar1 : bar0;
            uint32_t& ph = (s & 1) ? ph1 : ph0;
            mbar_wait_parity(b, ph);
            ph ^= 1;
            if (tid == 0)
                asm volatile("mbarrier.arrive.expect_tx.shared.b64 _, [%0], %1;" :: "r"(b), "r"(LL * 2) : "memory");
        }

        const __half* hc = h_s[s & 1];
        const int tok = (dir == 0) ? s : (TT - 1 - s);

        __half2 h2[4][4];
#pragma unroll
        for (int j = 0; j < 4; j++) {
            uint4 w = *(const uint4*)&hc[j * 64 + sl * 8];
            h2[j][0] = *reinterpret_cast<__half2*>(&w.x);
            h2[j][1] = *reinterpret_cast<__half2*>(&w.y);
            h2[j][2] = *reinterpret_cast<__half2*>(&w.z);
            h2[j][3] = *reinterpret_cast<__half2*>(&w.w);
        }

        __half2 a0 = __float2half2_rn(0.f), a1 = a0, a2 = a0, a3 = a0;
#pragma unroll
        for (int j = 0; j < 4; j++)
#pragma unroll
            for (int p = 0; p < 4; p++) {
                a0 = __hfma2(Ug[0][j][p], h2[j][p], a0);
                a1 = __hfma2(Ug[1][j][p], h2[j][p], a1);
                a2 = __hfma2(Ug[2][j][p], h2[j][p], a2);
                a3 = __hfma2(Ug[3][j][p], h2[j][p], a3);
            }
#pragma unroll
        for (int off = 4; off; off >>= 1) {
            a0 = __hadd2(a0, shfl_xor_h2(a0, off, 8));
            a1 = __hadd2(a1, shfl_xor_h2(a1, off, 8));
            a2 = __hadd2(a2, shfl_xor_h2(a2, off, 8));
            a3 = __hadd2(a3, shfl_xor_h2(a3, off, 8));
        }
        float acc0 = __low2float(a0) + __high2float(a0);
        float acc1 = __low2float(a1) + __high2float(a1);
        float acc2 = __low2float(a2) + __high2float(a2);
        float acc3 = __low2float(a3) + __high2float(a3);

        float iv = fsig_hw(acc0 + xwv0);
        float fv = fsig_hw(acc1 + xwv1);
        float gv = ftanh_hw(acc2 + xwv2);
        float ov = fsig_hw(acc3 + xwv3);
        c = fv * c + iv * gv;
        float hv = ov * ftanh_hw(c);

        if (s + 1 < TT) {
            uint32_t mine = (uint32_t)__half_as_ushort(__float2half(hv));
            uint32_t other = __shfl_xor_sync(0xffffffffu, mine, 8);
            if (pusher) {
                uint32_t pkt = mine | (other << 16);
                const uint32_t q = (s + 1) & 1;
                const uint32_t offH = q ? offH1 : 0u;
                const uint32_t offB = q ? offB1 : offB0;
                asm volatile(
                    "st.async.shared::cluster.mbarrier::complete_tx::bytes.b32 [%0], %1, [%2];"
                    :: "r"(dHme + offH), "r"(pkt), "r"(dHme + offB) : "memory");
            }
        }

        if (sl == 0)
            out[tok * (2 * LL) + coloff + u] = hv;

        if (s + 1 < TT) {
            const int ntok = (dir == 0) ? (s + 1) : (TT - 2 - s);
            const float* xp = &xw[ntok * ZDIM + u];
            xwv0 = __ldg(xp + 0 * LL);
            xwv1 = __ldg(xp + 1 * LL);
            xwv2 = __ldg(xp + 2 * LL);
            xwv3 = __ldg(xp + 3 * LL);
        }
    }

    asm volatile("barrier.cluster.arrive.aligned;" ::: "memory");
    asm volatile("barrier.cluster.wait.aligned;" ::: "memory");
}

// ---------------- pairwise head: out[i,j] = sum_h w[h]*tanh(hf[i,h]+mf[j,h]) + ob ----------------
__global__ void __launch_bounds__(256) pairwise_kernel(
    const float* __restrict__ headf, const float* __restrict__ modf,
    const float* __restrict__ outW, const float* __restrict__ outB,
    float* __restrict__ out) {
    __shared__ __align__(16) float SH[32][132];
    __shared__ float SMt[128][33];
    __shared__ __align__(16) float Wsh[128];

    const int t = threadIdx.x;
    const int i0 = blockIdx.y * 32, j0 = blockIdx.x * 32;
    const int li = t >> 3;
    const int lj = (t & 7) * 4;

    float acc0 = 0.f, acc1 = 0.f, acc2 = 0.f, acc3 = 0.f;

    for (int hc = 0; hc < HH; hc += 128) {
#pragma unroll
        for (int r = 0; r < 4; r++) {
            int idx = t + r * 256;
            int row = idx >> 5;
            int c4 = (idx & 31) * 4;
            float4 hvv = *(const float4*)&headf[(i0 + row) * HH + hc + c4];
            *(float4*)&SH[row][c4] = hvv;
            float4 mvv = *(const float4*)&modf[(j0 + row) * HH + hc + c4];
            SMt[c4 + 0][row] = mvv.x; SMt[c4 + 1][row] = mvv.y;
            SMt[c4 + 2][row] = mvv.z; SMt[c4 + 3][row] = mvv.w;
        }
        if (t < 32) *(float4*)&Wsh[t * 4] = *(const float4*)&outW[hc + t * 4];
        __syncthreads();

#pragma unroll 4
        for (int h = 0; h < 128; h++) {
            float hv = SH[li][h];
            float w = Wsh[h];
            acc0 += w * ftanh_hw(hv + SMt[h][lj + 0]);
            acc1 += w * ftanh_hw(hv + SMt[h][lj + 1]);
            acc2 += w * ftanh_hw(hv + SMt[h][lj + 2]);
            acc3 += w * ftanh_hw(hv + SMt[h][lj + 3]);
        }
        __syncthreads();
    }

    const float ob = outB[0];
    float* orow = &out[(i0 + li) * TT + j0 + lj];
    orow[0] = acc0 + ob;
    orow[1] = acc1 + ob;
    orow[2] = acc2 + ob;
    orow[3] = acc3 + ob;
}

// ---------------- host side ----------------
extern "C" void kernel_launch(void* const* d_in, const int* in_sizes, int n_in,
                              void* d_out, int out_size) {
    (void)in_sizes; (void)n_in; (void)out_size;
    const float* emb     = (const float*)d_in[0];
    const float* W_f1    = (const float*)d_in[1];
    const float* U_f1    = (const float*)d_in[2];
    const float* b_f1    = (const float*)d_in[3];
    const float* W_b1    = (const float*)d_in[4];
    const float* U_b1    = (const float*)d_in[5];
    const float* b_b1    = (const float*)d_in[6];
    const float* W_f2    = (const float*)d_in[7];
    const float* U_f2    = (const float*)d_in[8];
    const float* b_f2    = (const float*)d_in[9];
    const float* W_b2    = (const float*)d_in[10];
    const float* U_b2    = (const float*)d_in[11];
    const float* b_b2    = (const float*)d_in[12];
    const float* FOH     = (const float*)d_in[13];
    const float* FOM     = (const float*)d_in[14];
    const float* hidBias = (const float*)d_in[15];
    const float* outW    = (const float*)d_in[16];
    const float* outBias = (const float*)d_in[17];

    float *xwa, *xwb, *v, *hcat, *headf, *modf;
    cudaGetSymbolAddress((void**)&xwa,   g_xw_a);
    cudaGetSymbolAddress((void**)&xwb,   g_xw_b);
    cudaGetSymbolAddress((void**)&v,     g_v);
    cudaGetSymbolAddress((void**)&hcat,  g_hcat);
    cudaGetSymbolAddress((void**)&headf, g_headf);
    cudaGetSymbolAddress((void**)&modf,  g_modf);

    // 1. transpose + fp16-convert all recurrent matrices
    transposeU_kernel<<<dim3(ZDIM / 32, LL / 32, 4), dim3(32, 8)>>>(U_f1, U_b1, U_f2, U_b2);

    // 2. layer-1 input projections (tensor-core fp16 x fp32-accum)
    gemm2t_kernel<<<dim3(ZDIM / 64, TT / 64, 2), 256>>>(
        emb, emb, W_f1, W_b1, b_f1, b_b1, xwa, xwb, TT, ZDIM, DD);

    // 3. layer-1 BiLSTM
    lstm_cluster_kernel<<<2 * CLU, 256>>>(0);

    // 4. layer-2 input projections (tensor-core)
    gemm2t_kernel<<<dim3(ZDIM / 64, TT / 64, 2), 256>>>(
        v, v, W_f2, W_b2, b_f2, b_b2, xwa, xwb, TT, ZDIM, 2 * LL);

    // 5. layer-2 BiLSTM -> hcat
    lstm_cluster_kernel<<<2 * CLU, 256>>>(1);

    // 6. head projections (tensor-core as well; score-path error ~2e-4, margin ~4x)
    gemm2t_kernel<<<dim3(HH / 64, TT / 64, 2), 256>>>(
        hcat, hcat, FOH, FOM, hidBias, nullptr, headf, modf, TT, HH, 2 * LL);

    // 7. pairwise scores
    pairwise_kernel<<<dim3(TT / 32, TT / 32), 256>>>(headf, modf, outW, outBias, (float*)d_out);
}